// round 2
// baseline (speedup 1.0000x reference)
#include <cuda_runtime.h>
#include <cuda_bf16.h>
#include <cstdint>

// W8A16 linear: out[M,N] = (x[M,K] @ W[N,K]^T) * scales[N] + bias[N]
// x fp32, W int8 values delivered as an int32 buffer (harness dtype
// normalization), scales/bias fp32, out fp32.
// Accuracy: x split into hi+lo bf16; two bf16 MMA passes accumulate in fp32.
//
// Tiling: CTA 128x128, BK=32, 8 warps in 4(m) x 2(n), warp tile 32x64,
// mma.sync.aligned.m16n8k16.row.col.f32.bf16.bf16.f32

#define BM 128
#define BN 128
#define BK 32
#define KPAD 40   // smem row stride in halves (80B) -> conflict-free quad loads

__global__ __launch_bounds__(256, 2)
void w8a16_mma_kernel(const float* __restrict__ x,
                      const int* __restrict__ w,     // int8 values in int32 storage
                      const float* __restrict__ scales,
                      const float* __restrict__ bias,
                      float* __restrict__ out,
                      int M, int N, int K)
{
    __shared__ __nv_bfloat16 Ahi[BM][KPAD];
    __shared__ __nv_bfloat16 Alo[BM][KPAD];
    __shared__ __nv_bfloat16 Bsm[BN][KPAD];

    const int tid  = threadIdx.x;
    const int lane = tid & 31;
    const int warp = tid >> 5;
    const int wm = warp >> 1;        // 0..3
    const int wn = warp & 1;         // 0..1
    const int m_w = wm * 32;
    const int n_w = wn * 64;

    const float* xblk = x + (size_t)blockIdx.y * BM * K;
    const int*   wblk = w + (size_t)blockIdx.x * BN * K;

    float acc[2][8][4];
    #pragma unroll
    for (int mi = 0; mi < 2; ++mi)
        #pragma unroll
        for (int ni = 0; ni < 8; ++ni)
            #pragma unroll
            for (int c = 0; c < 4; ++c)
                acc[mi][ni][c] = 0.0f;

    for (int k0 = 0; k0 < K; k0 += BK) {
        // ---- Load A tile (128x32 fp32) -> hi/lo bf16 smem ----
        #pragma unroll
        for (int i = 0; i < 4; ++i) {
            int idx = tid + i * 256;          // 0..1023
            int row = idx >> 3;               // 0..127
            int kc  = (idx & 7) << 2;         // 0,4,...,28
            float4 v = *reinterpret_cast<const float4*>(xblk + (size_t)row * K + k0 + kc);

            __nv_bfloat16 h0 = __float2bfloat16(v.x);
            __nv_bfloat16 h1 = __float2bfloat16(v.y);
            __nv_bfloat16 h2 = __float2bfloat16(v.z);
            __nv_bfloat16 h3 = __float2bfloat16(v.w);
            float l0 = v.x - __bfloat162float(h0);
            float l1 = v.y - __bfloat162float(h1);
            float l2 = v.z - __bfloat162float(h2);
            float l3 = v.w - __bfloat162float(h3);

            *reinterpret_cast<__nv_bfloat162*>(&Ahi[row][kc])     = __halves2bfloat162(h0, h1);
            *reinterpret_cast<__nv_bfloat162*>(&Ahi[row][kc + 2]) = __halves2bfloat162(h2, h3);
            *reinterpret_cast<__nv_bfloat162*>(&Alo[row][kc])     = __floats2bfloat162_rn(l0, l1);
            *reinterpret_cast<__nv_bfloat162*>(&Alo[row][kc + 2]) = __floats2bfloat162_rn(l2, l3);
        }

        // ---- Load B tile (128x32 int32-stored weights) -> bf16 smem (exact) ----
        #pragma unroll
        for (int i = 0; i < 4; ++i) {
            int idx = tid + i * 256;
            int row = idx >> 3;
            int kc  = (idx & 7) << 2;
            int4 c = *reinterpret_cast<const int4*>(wblk + (size_t)row * K + k0 + kc);
            *reinterpret_cast<__nv_bfloat162*>(&Bsm[row][kc])     =
                __floats2bfloat162_rn((float)c.x, (float)c.y);
            *reinterpret_cast<__nv_bfloat162*>(&Bsm[row][kc + 2]) =
                __floats2bfloat162_rn((float)c.z, (float)c.w);
        }

        __syncthreads();

        #pragma unroll
        for (int ks = 0; ks < BK; ks += 16) {
            // B fragments: thread holds B[k=(lane%4)*2 + {0,1,8,9}][n=lane/4]
            uint32_t bf[8][2];
            #pragma unroll
            for (int ni = 0; ni < 8; ++ni) {
                int n  = n_w + ni * 8 + (lane >> 2);
                int kc = ks + ((lane & 3) << 1);
                bf[ni][0] = *reinterpret_cast<const uint32_t*>(&Bsm[n][kc]);
                bf[ni][1] = *reinterpret_cast<const uint32_t*>(&Bsm[n][kc + 8]);
            }

            #pragma unroll
            for (int hl = 0; hl < 2; ++hl) {
                const __nv_bfloat16 (*src)[KPAD] = hl ? Alo : Ahi;
                uint32_t af[2][4];
                #pragma unroll
                for (int mi = 0; mi < 2; ++mi) {
                    int r  = m_w + mi * 16 + (lane >> 2);
                    int kc = ks + ((lane & 3) << 1);
                    af[mi][0] = *reinterpret_cast<const uint32_t*>(&src[r][kc]);
                    af[mi][1] = *reinterpret_cast<const uint32_t*>(&src[r + 8][kc]);
                    af[mi][2] = *reinterpret_cast<const uint32_t*>(&src[r][kc + 8]);
                    af[mi][3] = *reinterpret_cast<const uint32_t*>(&src[r + 8][kc + 8]);
                }

                #pragma unroll
                for (int mi = 0; mi < 2; ++mi) {
                    #pragma unroll
                    for (int ni = 0; ni < 8; ++ni) {
                        asm volatile(
                            "mma.sync.aligned.m16n8k16.row.col.f32.bf16.bf16.f32 "
                            "{%0,%1,%2,%3}, {%4,%5,%6,%7}, {%8,%9}, {%0,%1,%2,%3};\n"
                            : "+f"(acc[mi][ni][0]), "+f"(acc[mi][ni][1]),
                              "+f"(acc[mi][ni][2]), "+f"(acc[mi][ni][3])
                            : "r"(af[mi][0]), "r"(af[mi][1]),
                              "r"(af[mi][2]), "r"(af[mi][3]),
                              "r"(bf[ni][0]), "r"(bf[ni][1]));
                    }
                }
            }
        }

        __syncthreads();
    }

    // ---- Epilogue: y = acc * scales[n] + bias[n] ----
    const int mbase = blockIdx.y * BM;
    const int nbase = blockIdx.x * BN;
    #pragma unroll
    for (int mi = 0; mi < 2; ++mi) {
        #pragma unroll
        for (int ni = 0; ni < 8; ++ni) {
            int r  = mbase + m_w + mi * 16 + (lane >> 2);
            int gn = nbase + n_w + ni * 8 + ((lane & 3) << 1);
            float s0 = scales[gn],     s1 = scales[gn + 1];
            float b0 = bias[gn],       b1 = bias[gn + 1];
            float2 v;
            v.x = acc[mi][ni][0] * s0 + b0;
            v.y = acc[mi][ni][1] * s1 + b1;
            *reinterpret_cast<float2*>(out + (size_t)r * N + gn) = v;
            v.x = acc[mi][ni][2] * s0 + b0;
            v.y = acc[mi][ni][3] * s1 + b1;
            *reinterpret_cast<float2*>(out + (size_t)(r + 8) * N + gn) = v;
        }
    }
}

extern "C" void kernel_launch(void* const* d_in, const int* in_sizes, int n_in,
                              void* d_out, int out_size)
{
    const float* x      = (const float*) d_in[0];
    const int*   w      = (const int*)   d_in[1];   // int8 values, int32 storage
    const float* scales = (const float*) d_in[2];
    const float* bias   = (const float*) d_in[3];
    float*       out    = (float*)       d_out;

    const int N = in_sizes[2];            // 11008 (scales count)
    const int K = in_sizes[1] / N;        // 4096
    const int M = in_sizes[0] / K;        // 4096 (= B*S)

    dim3 grid(N / BN, M / BM);            // 86 x 32
    w8a16_mma_kernel<<<grid, 256>>>(x, w, scales, bias, out, M, N, K);
}